// round 5
// baseline (speedup 1.0000x reference)
#include <cuda_runtime.h>

// SFAM_43490838839386: f = clip(tanh(x)/||tanh(x)||_2 + 0.01*noise, -1.5, 1.5)
//                      out = tanh(einsum('bi,bij->bj', f, P))
// B=4096, D=256, S=256, fp32. HBM-bound: P = 1.07 GB read once.
// R4 = R3 resubmit (infra failure): cp.async prefetch of first 4 P-iterations
// overlaps the phase-1 dependency chain (raw/noise load + norm reduce), so
// each CTA-slot streams DRAM from cycle ~0 instead of after a ~1200-cycle head.

#define Dk 256
#define Sk 256
#define NOISE_STD 0.01f
#define EPSN 1e-12f
#define PF 4   // prefetched i-iterations per thread

__global__ __launch_bounds__(256, 8)
void sfam_kernel(const float* __restrict__ raw,
                 const float* __restrict__ proj,
                 const float* __restrict__ noise,
                 float* __restrict__ out)
{
    __shared__ float  f_sh[Dk];
    __shared__ float  red[8 * 128];
    __shared__ float  warp_sums[8];
    __shared__ float4 pf_buf[PF][256];

    const int b    = blockIdx.x >> 1;   // sample
    const int half = blockIdx.x & 1;    // which 128-column half
    const int tid  = threadIdx.x;

    const int jg     = tid & 31;   // column group within half (float4)
    const int islice = tid >> 5;   // 0..7

    const float* pbase = proj + (size_t)b * Dk * Sk + (size_t)half * 128 + (size_t)jg * 4;

    // Critical-path loads for phase 1 first.
    const float rawv   = raw[(size_t)b * Dk + tid];
    const float noisev = noise[(size_t)b * Dk + tid];

    // Fire-and-forget prefetch of first PF iterations of P (register-free).
    {
        unsigned sbase = (unsigned)__cvta_generic_to_shared(&pf_buf[0][tid]);
        #pragma unroll
        for (int k = 0; k < PF; k++) {
            const float* g = pbase + (size_t)(islice + 8 * k) * Sk;
            asm volatile("cp.async.cg.shared.global [%0], [%1], 16;\n"
                         :: "r"(sbase + k * 256 * 16), "l"(g));
        }
        asm volatile("cp.async.commit_group;\n");
    }

    // ---------------- Phase 1: build f[b, :] in shared ----------------
    const float t = tanhf(rawv);
    float sq = t * t;
    #pragma unroll
    for (int o = 16; o > 0; o >>= 1)
        sq += __shfl_xor_sync(0xffffffffu, sq, o);
    const int lane = tid & 31;
    const int wid  = tid >> 5;
    if (lane == 0) warp_sums[wid] = sq;
    __syncthreads();
    if (tid < 8) {
        float v = warp_sums[tid];
        #pragma unroll
        for (int o = 4; o > 0; o >>= 1)
            v += __shfl_xor_sync(0xffu, v, o);
        if (tid == 0) warp_sums[0] = v;
    }
    __syncthreads();
    const float inv = 1.0f / fmaxf(sqrtf(warp_sums[0]), EPSN);

    float fv = fmaf(t, inv, NOISE_STD * noisev);
    fv = fminf(fmaxf(fv, -1.5f), 1.5f);
    f_sh[tid] = fv;
    __syncthreads();

    // ---------------- Phase 2: hashed[j] = sum_i f[i] * P[b,i,j] ----------------
    float4 acc = make_float4(0.f, 0.f, 0.f, 0.f);

    // Consume prefetched chunks (each thread reads only its own slots).
    asm volatile("cp.async.wait_group 0;\n" ::: "memory");
    #pragma unroll
    for (int k = 0; k < PF; k++) {
        const float  fi = f_sh[islice + 8 * k];
        const float4 p  = pf_buf[k][tid];
        acc.x = fmaf(fi, p.x, acc.x);
        acc.y = fmaf(fi, p.y, acc.y);
        acc.z = fmaf(fi, p.z, acc.z);
        acc.w = fmaf(fi, p.w, acc.w);
    }

    // Remaining 28 iterations: direct streaming loads.
    #pragma unroll 4
    for (int i = islice + 8 * PF; i < Dk; i += 8) {
        const float  fi = f_sh[i];
        const float4 p  = __ldcs(reinterpret_cast<const float4*>(pbase + (size_t)i * Sk));
        acc.x = fmaf(fi, p.x, acc.x);
        acc.y = fmaf(fi, p.y, acc.y);
        acc.z = fmaf(fi, p.z, acc.z);
        acc.w = fmaf(fi, p.w, acc.w);
    }

    *reinterpret_cast<float4*>(&red[islice * 128 + jg * 4]) = acc;
    __syncthreads();

    // Reduce 8 slices per column, final tanh, streaming store.
    if (tid < 128) {
        float h = 0.f;
        #pragma unroll
        for (int s = 0; s < 8; s++) h += red[s * 128 + tid];
        __stcs(&out[(size_t)b * Sk + (size_t)half * 128 + tid], tanhf(h));
    }
}

extern "C" void kernel_launch(void* const* d_in, const int* in_sizes, int n_in,
                              void* d_out, int out_size)
{
    const float* raw   = (const float*)d_in[0];
    const float* proj  = (const float*)d_in[1];
    const float* noise = (const float*)d_in[2];
    float* out = (float*)d_out;

    const int B = in_sizes[0] / Dk;  // 4096
    sfam_kernel<<<2 * B, 256>>>(raw, proj, noise, out);
}